// round 6
// baseline (speedup 1.0000x reference)
#include <cuda_runtime.h>
#include <cuda_bf16.h>

#define N_NODES_MAX 10000
#define E_MAX       320000
#define C           128
#define K2          256     // fused K: [agg | x]
#define STRIDE      192     // padded adjacency slots per node (deg mean 64, sd 8)

typedef unsigned long long ull;

// ---- device scratch ----
__device__ int   g_deg[N_NODES_MAX];
__device__ int   g_adj[N_NODES_MAX * STRIDE];
__device__ float g_agg[N_NODES_MAX * C];
// fused weights, k-major, NOT duplicated: g_wt[k*C + c] = (k<128)? w[c][k] : b[c][k-128]
__device__ float g_wt[K2 * C];

// ---- packed fp32x2 helpers ----
__device__ __forceinline__ void upk(float& lo, float& hi, ull v) {
    asm("mov.b64 {%0, %1}, %2;" : "=f"(lo), "=f"(hi) : "l"(v));
}
__device__ __forceinline__ void fma2(ull& d, ull a, ull b) {
    asm("fma.rn.f32x2 %0, %1, %2, %0;" : "+l"(d) : "l"(a), "l"(b));
}

// ---------------------------------------------------------------------------
// 1) init: zero degree counters + build fused weight matrix (k-major)
// ---------------------------------------------------------------------------
__global__ void k_init(const float* __restrict__ w,
                       const float* __restrict__ b, int n) {
    int idx = blockIdx.x * blockDim.x + threadIdx.x;   // 0..32767
    if (idx < n) g_deg[idx] = 0;
    if (idx < K2 * C) {
        int k = idx >> 7;          // 0..255
        int c = idx & (C - 1);     // 0..127
        g_wt[idx] = (k < C) ? w[c * C + k] : b[c * C + (k - C)];
    }
}

// ---------------------------------------------------------------------------
// 2) fill padded adjacency: edge (i,j) -> adj[i] += j, adj[j] += i
// ---------------------------------------------------------------------------
__global__ void k_fill(const int* __restrict__ ei, int e, int n) {
    int k = blockIdx.x * blockDim.x + threadIdx.x;
    if (k >= e) return;
    int2 p = ((const int2*)ei)[k];
    int i = p.x, j = p.y;
    if ((unsigned)i >= (unsigned)n || (unsigned)j >= (unsigned)n) return;
    int si = atomicAdd(&g_deg[i], 1);
    if (si < STRIDE) g_adj[i * STRIDE + si] = j;
    int sj = atomicAdd(&g_deg[j], 1);
    if (sj < STRIDE) g_adj[j * STRIDE + sj] = i;
}

// ---------------------------------------------------------------------------
// 3) mean aggregation: one warp per node, lane owns float4 (4 channels)
// ---------------------------------------------------------------------------
__global__ void k_agg(const float* __restrict__ x, int n) {
    int warp = (blockIdx.x * blockDim.x + threadIdx.x) >> 5;
    if (warp >= n) return;
    int lane = threadIdx.x & 31;
    int deg = g_deg[warp];
    int cnt = deg < STRIDE ? deg : STRIDE;
    const int* adj = &g_adj[warp * STRIDE];

    float4 a0 = make_float4(0.f, 0.f, 0.f, 0.f);
    float4 a1 = a0, a2 = a0, a3 = a0;

    const float4* x4 = (const float4*)x;
    int i = 0;
    for (; i + 3 < cnt; i += 4) {
        int m0 = adj[i], m1 = adj[i + 1], m2 = adj[i + 2], m3 = adj[i + 3];
        float4 v0 = x4[m0 * 32 + lane];
        float4 v1 = x4[m1 * 32 + lane];
        float4 v2 = x4[m2 * 32 + lane];
        float4 v3 = x4[m3 * 32 + lane];
        a0.x += v0.x; a0.y += v0.y; a0.z += v0.z; a0.w += v0.w;
        a1.x += v1.x; a1.y += v1.y; a1.z += v1.z; a1.w += v1.w;
        a2.x += v2.x; a2.y += v2.y; a2.z += v2.z; a2.w += v2.w;
        a3.x += v3.x; a3.y += v3.y; a3.z += v3.z; a3.w += v3.w;
    }
    for (; i < cnt; i++) {
        float4 v = x4[adj[i] * 32 + lane];
        a0.x += v.x; a0.y += v.y; a0.z += v.z; a0.w += v.w;
    }
    a0.x += a1.x + a2.x + a3.x;
    a0.y += a1.y + a2.y + a3.y;
    a0.z += a1.z + a2.z + a3.z;
    a0.w += a1.w + a2.w + a3.w;

    float inv = (deg > 0) ? 1.0f / (float)deg : 0.0f;
    ((float4*)g_agg)[warp * 32 + lane] =
        make_float4(a0.x * inv, a0.y * inv, a0.z * inv, a0.w * inv);
}

// ---------------------------------------------------------------------------
// 4) tiled fused SGEMM + ReLU, f32x2, 8-node x 8-channel register tile.
//    out = relu(A2 @ W2), M=10000, N=128, K=256.
//    Block = 64 threads (2 warps); tile = 32 nodes x 128 channels.
//    Warp w covers channels 64w..64w+63; lane: ng=lane&3 -> nodes ng*8..+7,
//    cg=lane>>2 -> channels 8cg..8cg+7.
//    Weights: non-duplicated k-major -> 1 ulonglong2 = 2 ready f32x2 (ch pairs).
//    Acts: duplicated float2 in smem -> 1 ulonglong2 = 2 ready broadcast f32x2.
//    Per thread per k: 2 LDG.128 + 4 LDS.128 feed 32 FFMA2 (1.0 FMA/byte).
// ---------------------------------------------------------------------------
#define MT 32
#define KC 64

__global__ void __launch_bounds__(64) k_gemm(const float* __restrict__ x,
                                             float* __restrict__ out, int n) {
    __shared__ __align__(16) float2 s_a[KC][MT];   // duplicated acts, 16 KB

    const int tid  = threadIdx.x;        // 0..63
    const int lane = tid & 31;
    const int wrp  = tid >> 5;           // 0..1
    const int m0   = blockIdx.x * MT;
    const int ng   = lane & 3;           // node group: nodes ng*8..ng*8+7
    const int cg   = lane >> 2;          // 0..7
    const int ch0  = wrp * 64 + cg * 8;  // 8 channels per thread

    ull acc[8][4];                        // [node][channel pair]; 0 == (0.f,0.f)
    #pragma unroll
    for (int nd = 0; nd < 8; nd++)
        #pragma unroll
        for (int cp = 0; cp < 4; cp++) acc[nd][cp] = 0ull;

    const ulonglong2* wt2 = (const ulonglong2*)g_wt;   // row k = 32 ulonglong2

    for (int kc = 0; kc < K2; kc += KC) {
        // ---- stage A2 chunk transposed + duplicated: s_a[k][node] = (a,a) ----
        __syncthreads();
        const float* src = (kc < C) ? g_agg : x;
        const int koff = kc & (C - 1);
        #pragma unroll
        for (int r = 0; r < 8; r++) {
            int idx  = (r << 6) + tid;       // 0..511
            int node = idx & (MT - 1);
            int kq   = idx >> 5;             // 0..15 -> k = kq*4
            int gn   = m0 + node;
            float4 v = make_float4(0.f, 0.f, 0.f, 0.f);
            if (gn < n) v = *(const float4*)&src[(size_t)gn * C + koff + kq * 4];
            s_a[kq * 4 + 0][node] = make_float2(v.x, v.x);
            s_a[kq * 4 + 1][node] = make_float2(v.y, v.y);
            s_a[kq * 4 + 2][node] = make_float2(v.z, v.z);
            s_a[kq * 4 + 3][node] = make_float2(v.w, v.w);
        }
        __syncthreads();

        #pragma unroll 2
        for (int k = 0; k < KC; k++) {
            size_t widx = (size_t)(kc + k) * 32 + wrp * 16 + cg * 2;
            ulonglong2 w01 = __ldg(wt2 + widx);       // ch pairs 0,1
            ulonglong2 w23 = __ldg(wt2 + widx + 1);   // ch pairs 2,3
            ull wv[4] = {w01.x, w01.y, w23.x, w23.y};

            const ulonglong2* ap = (const ulonglong2*)&s_a[k][ng * 8];
            ulonglong2 p0 = ap[0], p1 = ap[1], p2 = ap[2], p3 = ap[3];
            ull av[8] = {p0.x, p0.y, p1.x, p1.y, p2.x, p2.y, p3.x, p3.y};

            #pragma unroll
            for (int nd = 0; nd < 8; nd++)
                #pragma unroll
                for (int cp = 0; cp < 4; cp++)
                    fma2(acc[nd][cp], av[nd], wv[cp]);
        }
    }

    // ---- epilogue: relu + store 8 channels per node as 2x float4 ----
    #pragma unroll
    for (int nd = 0; nd < 8; nd++) {
        int node = m0 + ng * 8 + nd;
        if (node >= n) continue;
        float f[8];
        #pragma unroll
        for (int cp = 0; cp < 4; cp++) upk(f[2 * cp], f[2 * cp + 1], acc[nd][cp]);
        float4 lo = make_float4(fmaxf(f[0], 0.f), fmaxf(f[1], 0.f),
                                fmaxf(f[2], 0.f), fmaxf(f[3], 0.f));
        float4 hi = make_float4(fmaxf(f[4], 0.f), fmaxf(f[5], 0.f),
                                fmaxf(f[6], 0.f), fmaxf(f[7], 0.f));
        *(float4*)&out[(size_t)node * C + ch0]     = lo;
        *(float4*)&out[(size_t)node * C + ch0 + 4] = hi;
    }
}

// ---------------------------------------------------------------------------
extern "C" void kernel_launch(void* const* d_in, const int* in_sizes, int n_in,
                              void* d_out, int out_size) {
    const float* x  = (const float*)d_in[0];
    const int*   ei = (const int*)d_in[1];
    const float* w  = (const float*)d_in[2];
    const float* b  = (const float*)d_in[3];
    float*       out = (float*)d_out;

    int n = in_sizes[0] / C;     // 10000
    int e = in_sizes[1] / 2;     // 320000

    k_init<<<(K2 * C + 255) / 256, 256>>>(w, b, n);
    k_fill<<<(e + 255) / 256, 256>>>(ei, e, n);
    k_agg <<<(n * 32 + 255) / 256, 256>>>(x, n);

    k_gemm<<<(n + MT - 1) / MT, 64>>>(x, out, n);
}